// round 17
// baseline (speedup 1.0000x reference)
#include <cuda_runtime.h>
#include <math.h>

#define LMAX 20
#define NK   210           // LMAX*(LMAX+1)/2
#define NCOL 400
#define T    256           // threads/block
#define PTS  64            // points/block (4 threads per point)
#define STRIDE 145         // smem row stride; 145 mod 32 = 17 (see writeback proof)
#define NM   5             // m values per thread (m = par + 4j)
#define NWARP (T / 32)

// ---------------- compile-time tables ----------------
constexpr double csqrt(double x) {
    if (x <= 0.0) return 0.0;
    double scale = 1.0;
    while (x > 4.0)  { x *= 0.25; scale *= 2.0; }
    while (x < 0.25) { x *= 4.0;  scale *= 0.5; }
    double g = 1.0;
    for (int i = 0; i < 48; ++i) g = 0.5 * (g + x / g);
    return g * scale;
}

struct Tables {
    float ax[NK];    // A coeff
    float bx[NK];    // B coeff
    float d4[LMAX];  // skip-4 sectoral diagonal coeff (valid for m>=4)
    float sd[4];     // seeds: Kbar(m,m) coefficient, m=0..3 (times sx^m)
};

constexpr Tables make_tables() {
    Tables t{};
    for (int l = 0; l < LMAX; ++l) {
        for (int m = 0; m <= l; ++m) {
            int idx = l * (l + 1) / 2 + m;
            double A = 0.0, Bc = 0.0;
            if (l >= m + 1) {
                A = csqrt((double)((2 * l + 1) * (2 * l - 1)) /
                          (double)((l - m) * (l + m)));
                if (l >= m + 2) {
                    double r = (double)(2 * l + 1) / (double)(2 * l - 3)
                             * (double)((l - m) * (l - m - 1))
                             / (double)((l + m) * (l + m - 1));
                    Bc = (double)(l + m - 1) / (double)(l - m) * csqrt(r);
                }
            }
            t.ax[idx] = (float)A;
            t.bx[idx] = (float)Bc;
        }
    }
    // skip-4 diagonal: Pbar(m,m) = d4(m) * sx^4 * Pbar(m-4,m-4)
    for (int m = 4; m < LMAX; ++m) {
        double prodOdd = 1.0;
        for (int k = 0; k < 4; ++k) prodOdd *= (double)(2 * m - 1 - 2 * k);
        double prodFact = 1.0;
        for (int k = 0; k < 8; ++k) prodFact *= (double)(2 * m - k);
        t.d4[m] = (float)(prodOdd *
            csqrt((double)(2 * m + 1) / (double)(2 * m - 7) / prodFact));
    }
    // seeds: (-1)^m (2m-1)!! sqrt((2m+1)/(4pi (2m)!))   (sqrt2 lives in CM/SM)
    const double PI = 3.14159265358979323846;
    for (int m = 0; m < 4; ++m) {
        double dfac = 1.0;
        for (int k = 1; k <= 2 * m - 1; k += 2) dfac *= (double)k;
        double fact = 1.0;
        for (int k = 2; k <= 2 * m; ++k) fact *= (double)k;
        double v = dfac * csqrt((double)(2 * m + 1) / (4.0 * PI * fact));
        t.sd[m] = (float)((m & 1) ? -v : v);
    }
    return t;
}

__device__ const Tables g_tab = make_tables();

// Rows l in [L0,L1); this thread handles m = PAR + 4j. Emits cols - CBASE.
template<int L0, int L1, int CBASE, int PAR>
__device__ __forceinline__ void compute_rows(
    float* __restrict__ row, const float2* __restrict__ sAB,
    const float* __restrict__ sD4,
    float x, float sx4, float seed,
    const float (&CM)[NM], const float (&SM)[NM],
    float (&Pa)[NM], float (&Pb)[NM], float& diag)
{
    #pragma unroll
    for (int l = L0; l < L1; ++l) {
        float Pn[NM];
        #pragma unroll
        for (int j = 0; j < NM; ++j) {
            const int m = PAR + 4 * j;
            if (m > l) continue;
            if (m == l) {
                Pn[j] = (j == 0) ? seed : sD4[l] * sx4 * diag;
                diag = Pn[j];
            } else {
                float2 ab = sAB[l * (l + 1) / 2 + m];   // LDS.64 broadcast
                Pn[j] = fmaf(ab.x * x, Pa[j], -(ab.y * Pb[j]));
            }
        }
        const int base = l * l + l - CBASE;
        #pragma unroll
        for (int j = 0; j < NM; ++j) {
            const int m = PAR + 4 * j;
            if (m > l) continue;
            float t = Pn[j];
            if (m == 0) row[base] = t;
            else { row[base + m] = t * CM[j]; row[base - m] = t * SM[j]; }
        }
        #pragma unroll
        for (int j = 0; j < NM; ++j) {
            const int m = PAR + 4 * j;
            if (m > l) continue;
            Pb[j] = Pa[j]; Pa[j] = Pn[j];
        }
    }
}

// Float4-gather writeback. Warp layout: lane = (rsub = lane>>3, c4 = lane&7)
// -> 4 rows x 8 float4s per pass. Each thread gathers 4 consecutive floats
// from its own smem row (4x LDS.32, MLP-4) and issues one STG.128.
// Bank proof (STRIDE=145, 145 mod 32 = 17): bank = (17*rsub + 4*c4 + j) mod 32;
// 17*rsub mod 4 = {0,1,2,3} -> the 4 row-groups occupy disjoint mod-4 bank
// classes and 4*c4 spans each class -> all 32 banks hit, conflict-free per j.
// Gmem: NCOL%4==0 and CBASE%4==0 -> 16B-aligned STG.128; 8 lanes = 128B/row.
template<int CBASE, int COLS>
__device__ __forceinline__ void writeback(
    const float* __restrict__ sh, float* __restrict__ out,
    int p0, int np, int warp, int lane)
{
    constexpr int NF4   = COLS / 4;          // float4s per row (36/28/36)
    constexpr int NPASS = NF4 / 8;           // full 8-wide passes
    constexpr int REM4  = NF4 - NPASS * 8;   // leftover float4s (<8)
    const int rsub = lane >> 3;              // 0..3
    const int c4l  = lane & 7;               // 0..7

    for (int r0 = warp * 4; r0 < np; r0 += NWARP * 4) {
        int r = r0 + rsub;
        if (r >= np) continue;
        const float* s = sh + r * STRIDE;
        float* d = out + (size_t)(p0 + r) * NCOL + CBASE;
        #pragma unroll
        for (int pass = 0; pass < NPASS; ++pass) {
            const int c = (pass * 8 + c4l) * 4;
            float4 v;
            v.x = s[c + 0]; v.y = s[c + 1]; v.z = s[c + 2]; v.w = s[c + 3];
            *reinterpret_cast<float4*>(d + c) = v;
        }
        if (REM4 && c4l < REM4) {
            const int c = (NPASS * 8 + c4l) * 4;
            float4 v;
            v.x = s[c + 0]; v.y = s[c + 1]; v.z = s[c + 2]; v.w = s[c + 3];
            *reinterpret_cast<float4*>(d + c) = v;
        }
    }
}

__global__ __launch_bounds__(T, 5) void sh_kernel(
    const float* __restrict__ lonlat, float* __restrict__ out, int B)
{
    __shared__ float2 sAB[NK];
    __shared__ float  sD4[LMAX];
    extern __shared__ float sh[];

    const int tid  = threadIdx.x;
    const int lane = tid & 31;
    const int warp = tid >> 5;
    const int pt   = tid & (PTS - 1);
    const int par  = tid >> 6;               // m mod 4 class (warp-uniform)
    const int p0   = blockIdx.x * PTS;
    const int np   = min(PTS, B - p0);

    for (int i = tid; i < NK; i += T)
        sAB[i] = make_float2(g_tab.ax[i], g_tab.bx[i]);
    if (tid < LMAX) sD4[tid] = g_tab.d4[tid];
    __syncthreads();

    const bool active = (pt < np);
    float x = 0.f, sx4 = 0.f, seed = 0.f, diag = 0.f;
    float CM[NM], SM[NM], Pa[NM], Pb[NM];

    if (active) {
        float2 ll = reinterpret_cast<const float2*>(lonlat)[p0 + pt];
        const float d2r = 0.017453292519943295f;
        float phi   = (ll.x + 180.0f) * d2r;
        float theta = (ll.y +  90.0f) * d2r;
        x = cosf(theta);
        float sx = sinf(theta);
        float sx2 = sx * sx;
        sx4 = sx2 * sx2;
        float s1, c1;
        sincosf(phi, &s1, &c1);
        float c2 = c1 * c1 - s1 * s1;       // cos(2phi)
        float s2 = 2.0f * s1 * c1;          // sin(2phi)
        float c4 = c2 * c2 - s2 * s2;       // cos(4phi)
        float s4 = 2.0f * s2 * c2;          // sin(4phi)
        const float SQ2 = 1.41421356237309505f;
        float sxp;
        if (par == 0)      { CM[0] = SQ2;       SM[0] = 0.0f;      sxp = 1.0f; }
        else if (par == 1) { CM[0] = SQ2 * c1;  SM[0] = SQ2 * s1;  sxp = sx; }
        else if (par == 2) { CM[0] = SQ2 * c2;  SM[0] = SQ2 * s2;  sxp = sx2; }
        else               { float c3 = c1 * c2 - s1 * s2;
                             float s3 = s1 * c2 + c1 * s2;
                             CM[0] = SQ2 * c3;  SM[0] = SQ2 * s3;  sxp = sx2 * sx; }
        seed = g_tab.sd[par] * sxp;
        #pragma unroll
        for (int j = 1; j < NM; ++j) {
            CM[j] = CM[j - 1] * c4 - SM[j - 1] * s4;
            SM[j] = SM[j - 1] * c4 + CM[j - 1] * s4;
        }
        #pragma unroll
        for (int j = 0; j < NM; ++j) { Pa[j] = 0.0f; Pb[j] = 0.0f; }
    }

    float* row = sh + pt * STRIDE;

#define COMPUTE(L0, L1, CB)                                                       \
    if (active) {                                                                 \
        if      (par == 0) compute_rows<L0, L1, CB, 0>(row, sAB, sD4, x, sx4,     \
                                     seed, CM, SM, Pa, Pb, diag);                 \
        else if (par == 1) compute_rows<L0, L1, CB, 1>(row, sAB, sD4, x, sx4,     \
                                     seed, CM, SM, Pa, Pb, diag);                 \
        else if (par == 2) compute_rows<L0, L1, CB, 2>(row, sAB, sD4, x, sx4,     \
                                     seed, CM, SM, Pa, Pb, diag);                 \
        else               compute_rows<L0, L1, CB, 3>(row, sAB, sD4, x, sx4,     \
                                     seed, CM, SM, Pa, Pb, diag);                 \
    }

    // chunk 0: l 0..11  cols [0,144)
    COMPUTE(0, 12, 0)
    __syncthreads();
    writeback<0, 144>(sh, out, p0, np, warp, lane);
    __syncthreads();

    // chunk 1: l 12..15 cols [144,256)
    COMPUTE(12, 16, 144)
    __syncthreads();
    writeback<144, 112>(sh, out, p0, np, warp, lane);
    __syncthreads();

    // chunk 2: l 16..19 cols [256,400)
    COMPUTE(16, 20, 256)
    __syncthreads();
    writeback<256, 144>(sh, out, p0, np, warp, lane);
#undef COMPUTE
}

extern "C" void kernel_launch(void* const* d_in, const int* in_sizes, int n_in,
                              void* d_out, int out_size)
{
    const float* lonlat = (const float*)d_in[0];
    float* out = (float*)d_out;
    int B = in_sizes[0] / 2;

    size_t smem = (size_t)PTS * STRIDE * sizeof(float);   // 37,120 B dynamic
    cudaFuncSetAttribute(sh_kernel,
                         cudaFuncAttributeMaxDynamicSharedMemorySize, (int)smem);

    int grid = (B + PTS - 1) / PTS;
    sh_kernel<<<grid, T, smem>>>(lonlat, out, B);
}